// round 16
// baseline (speedup 1.0000x reference)
#include <cuda_runtime.h>
#include <cuda_fp16.h>
#include <cstdint>

#define T_TOK 16384
#define H_DIM 512
#define M_MEM 4096
#define EXP_SCALE 8192.0f

// ---------------------------------------------------------------------------
// Scratch (static device globals; no allocations anywhere)
// ---------------------------------------------------------------------------
__device__ __half g_hid_hi[(size_t)T_TOK * H_DIM];
__device__ __half g_wk_hi[(size_t)H_DIM * H_DIM];
__device__ __half g_wo_hi[(size_t)H_DIM * H_DIM];
__device__ __half g_mv_hi[(size_t)M_MEM * H_DIM];   // compacted mv
__device__ __half g_mk_hi[(size_t)M_MEM * H_DIM];   // compacted, normalized mk (hi only)
__device__ __half g_w2t_hi[(size_t)H_DIM * M_MEM];  // W2T over compacted bank (hi only)
__device__ __half g_q_hi[(size_t)T_TOK * H_DIM];    // q (+bk), fp16, unnormalized
__device__ __half g_exp[(size_t)T_TOK * M_MEM];     // exp(logit-10)*8192, compacted cols
__device__ float  g_qnorm[T_TOK];                   // sum q^2 per row (atomic)
__device__ float  g_rowsum[T_TOK];                  // sum exp per row (atomic)
__device__ int    g_idx[M_MEM];                     // compacted slot -> original slot
__device__ int    g_meta[2];                        // [0]=M_active, [1]=pad256(M_active)

// ---------------------------------------------------------------------------
// Helpers (baseline PTX only: cp.async / ldmatrix / mma.sync)
// ---------------------------------------------------------------------------
__device__ __forceinline__ uint32_t su32(const void* p) {
    return (uint32_t)__cvta_generic_to_shared(p);
}
__device__ __forceinline__ void cp16(uint32_t dst, const void* src) {
    asm volatile("cp.async.cg.shared.global [%0], [%1], 16;\n" :: "r"(dst), "l"(src) : "memory");
}
__device__ __forceinline__ void cp_commit() { asm volatile("cp.async.commit_group;\n" ::: "memory"); }
__device__ __forceinline__ void cp_wait1()  { asm volatile("cp.async.wait_group 1;\n" ::: "memory"); }

__device__ __forceinline__ void ldsm_x4(uint32_t* r, uint32_t addr) {
    asm volatile("ldmatrix.sync.aligned.m8n8.x4.shared.b16 {%0,%1,%2,%3}, [%4];"
                 : "=r"(r[0]), "=r"(r[1]), "=r"(r[2]), "=r"(r[3]) : "r"(addr));
}
__device__ __forceinline__ void mma16816(float* c, const uint32_t* a, const uint32_t* b) {
    asm volatile(
        "mma.sync.aligned.m16n8k16.row.col.f32.f16.f16.f32 "
        "{%0,%1,%2,%3}, {%4,%5,%6,%7}, {%8,%9}, {%0,%1,%2,%3};"
        : "+f"(c[0]), "+f"(c[1]), "+f"(c[2]), "+f"(c[3])
        : "r"(a[0]), "r"(a[1]), "r"(a[2]), "r"(a[3]), "r"(b[0]), "r"(b[1]));
}

// ---------------------------------------------------------------------------
// Compaction + accumulator zeroing. 1024 threads, single CTA.
// ---------------------------------------------------------------------------
__global__ void compact_kernel(const int* __restrict__ usage, int* __restrict__ idx,
                               int* __restrict__ meta,
                               float* __restrict__ qnorm, float* __restrict__ rowsum)
{
    __shared__ int wsum[32];
    const int t = threadIdx.x, lane = t & 31, w = t >> 5;

    // zero the row accumulators (16 floats per thread per array)
#pragma unroll
    for (int i = 0; i < 16; i++) {
        qnorm[t + (i << 10)]  = 0.0f;
        rowsum[t + (i << 10)] = 0.0f;
    }

    const int base = t * 4;
    int f[4], cnt = 0;
#pragma unroll
    for (int i = 0; i < 4; i++) { f[i] = usage[base + i] > 0; cnt += f[i]; }
    int inc = cnt;
#pragma unroll
    for (int o = 1; o < 32; o <<= 1) {
        int v = __shfl_up_sync(0xffffffffu, inc, o);
        if (lane >= o) inc += v;
    }
    const int exc = inc - cnt;
    if (lane == 31) wsum[w] = inc;
    __syncthreads();
    if (w == 0) {
        int v = wsum[lane];
        __syncwarp();
#pragma unroll
        for (int o = 1; o < 32; o <<= 1) {
            int u = __shfl_up_sync(0xffffffffu, v, o);
            if (lane >= o) v += u;
        }
        wsum[lane] = v;
    }
    __syncthreads();
    int pos = (w > 0 ? wsum[w - 1] : 0) + exc;
#pragma unroll
    for (int i = 0; i < 4; i++)
        if (f[i]) idx[pos++] = base + i;
    if (t == 1023) {
        const int tot = wsum[31];
        meta[0] = tot;
        int pad = ((tot + 255) >> 8) << 8;
        meta[1] = pad < 256 ? 256 : pad;
    }
}

// ---------------------------------------------------------------------------
// Bank prep: block j -> compacted row j: mv fp16 hi, mk normalized fp16 hi.
// ---------------------------------------------------------------------------
__global__ void prep_bank_kernel(const float* __restrict__ mv, const float* __restrict__ mk,
                                 const int* __restrict__ idx, const int* __restrict__ meta,
                                 __half* __restrict__ mvh, __half* __restrict__ mkh)
{
    __shared__ float sh[4];
    const int j = blockIdx.x, tid = threadIdx.x;
    const size_t off = (size_t)j * H_DIM + tid * 4;
    if (j >= meta[0]) {
        const __half2 z = __halves2half2(__float2half_rn(0.f), __float2half_rn(0.f));
        *(__half2*)(mvh + off + 0) = z; *(__half2*)(mvh + off + 2) = z;
        *(__half2*)(mkh + off + 0) = z; *(__half2*)(mkh + off + 2) = z;
        return;
    }
    const int row = idx[j];
    {
        float4 v = ((const float4*)(mv + (size_t)row * H_DIM))[tid];
        *(__half2*)(mvh + off + 0) = __halves2half2(__float2half_rn(v.x), __float2half_rn(v.y));
        *(__half2*)(mvh + off + 2) = __halves2half2(__float2half_rn(v.z), __float2half_rn(v.w));
    }
    {
        float4 v = ((const float4*)(mk + (size_t)row * H_DIM))[tid];
        float s = v.x * v.x + v.y * v.y + v.z * v.z + v.w * v.w;
#pragma unroll
        for (int o = 16; o; o >>= 1) s += __shfl_xor_sync(0xffffffffu, s, o);
        if ((tid & 31) == 0) sh[tid >> 5] = s;
        __syncthreads();
        const float r = rsqrtf(sh[0] + sh[1] + sh[2] + sh[3] + 1e-6f);
        *(__half2*)(mkh + off + 0) = __halves2half2(__float2half_rn(v.x * r), __float2half_rn(v.y * r));
        *(__half2*)(mkh + off + 2) = __halves2half2(__float2half_rn(v.z * r), __float2half_rn(v.w * r));
    }
}

// ---------------------------------------------------------------------------
// Weights prep: Wk -> hi, Wo -> hi. One thread per float4 of each.
// ---------------------------------------------------------------------------
__global__ void prep_w_kernel(const float* __restrict__ Wk, const float* __restrict__ Wo,
                              __half* __restrict__ wkh, __half* __restrict__ woh)
{
    const int idx = blockIdx.x * blockDim.x + threadIdx.x;
    {
        float4 v = ((const float4*)Wk)[idx];
        ((__half2*)wkh)[idx * 2 + 0] = __halves2half2(__float2half_rn(v.x), __float2half_rn(v.y));
        ((__half2*)wkh)[idx * 2 + 1] = __halves2half2(__float2half_rn(v.z), __float2half_rn(v.w));
    }
    {
        float4 v = ((const float4*)Wo)[idx];
        ((__half2*)woh)[idx * 2 + 0] = __halves2half2(__float2half_rn(v.x), __float2half_rn(v.y));
        ((__half2*)woh)[idx * 2 + 1] = __halves2half2(__float2half_rn(v.z), __float2half_rn(v.w));
    }
}

// ---------------------------------------------------------------------------
// Elementwise fp32 -> fp16 (hidden)
// ---------------------------------------------------------------------------
__global__ void convert_hi_kernel(const float* __restrict__ in, __half* __restrict__ oh, int n4)
{
    int idx = blockIdx.x * blockDim.x + threadIdx.x;
    const int stride = gridDim.x * blockDim.x;
    for (; idx < n4; idx += stride) {
        float4 v = ((const float4*)in)[idx];
        ((__half2*)oh)[idx * 2 + 0] = __halves2half2(__float2half_rn(v.x), __float2half_rn(v.y));
        ((__half2*)oh)[idx * 2 + 1] = __halves2half2(__float2half_rn(v.z), __float2half_rn(v.w));
    }
}

// ---------------------------------------------------------------------------
// Shared GEMM machinery: CTA tile 128x256, 8 warps (2x4) of 64x64, BK=64,
// 3-stage single-sync cp.async pipeline, fp32 accumulators.
// ---------------------------------------------------------------------------
#define BK       64
#define TROW     144
#define A_TSZ    (128 * TROW)              // 18432 B
#define B_TSZ    (256 * TROW)              // 36864 B
#define STG1     (A_TSZ + B_TSZ)           // 55296 B
#define MM_SMEM1 (3 * STG1)                // 165888

__device__ __forceinline__ void load_chunk(uint32_t st,
    const __half* __restrict__ A, const __half* __restrict__ B,
    int LD, int m0, int n0, int k0, int t)
{
#pragma unroll
    for (int i = 0; i < 4; i++) {
        const int idx = (i << 8) + t;
        const int row = idx >> 3, j = idx & 7;
        cp16(st + (uint32_t)(row * TROW + j * 16),
             A + (size_t)(m0 + row) * LD + k0 + (j << 3));
    }
#pragma unroll
    for (int i = 0; i < 8; i++) {
        const int idx = (i << 8) + t;
        const int row = idx >> 3, j = idx & 7;
        cp16(st + A_TSZ + (uint32_t)(row * TROW + j * 16),
             B + (size_t)(n0 + row) * LD + k0 + (j << 3));
    }
}

// mainloop: computes acc over K chunks for tile (m0, n0)
__device__ __forceinline__ void gemm_mainloop(
    float acc[4][8][4], uint32_t sb,
    const __half* __restrict__ A, const __half* __restrict__ B,
    int LD, int m0, int n0, int K, int t,
    uint32_t aoff, uint32_t boff)
{
    const int nch = K / BK;
    load_chunk(sb, A, B, LD, m0, n0, 0, t);         cp_commit();
    load_chunk(sb + STG1, A, B, LD, m0, n0, BK, t); cp_commit();
    for (int c = 0; c < nch; c++) {
        cp_wait1();
        __syncthreads();
        if (c + 2 < nch)
            load_chunk(sb + (uint32_t)((c + 2) % 3) * STG1, A, B,
                       LD, m0, n0, (c + 2) * BK, t);
        cp_commit();
        const uint32_t st = sb + (uint32_t)(c % 3) * STG1;
#pragma unroll
        for (int ks = 0; ks < 4; ks++) {
            uint32_t ah[4][4], bh[4][4];
#pragma unroll
            for (int mf = 0; mf < 4; mf++)
                ldsm_x4(ah[mf], st + aoff + mf * (16 * TROW) + ks * 32);
#pragma unroll
            for (int nf2 = 0; nf2 < 4; nf2++)
                ldsm_x4(bh[nf2], st + A_TSZ + boff + nf2 * (16 * TROW) + ks * 32);
#pragma unroll
            for (int mf = 0; mf < 4; mf++)
#pragma unroll
                for (int nf = 0; nf < 8; nf++)
                    mma16816(acc[mf][nf], ah[mf], &bh[nf >> 1][(nf & 1) * 2]);
        }
    }
}

// ---------------------------------------------------------------------------
// Combined qproj + W2T kernel. 1D grid of 256+64 blocks.
//   bid < 256 : qproj tile  (m-tile = bid>>1, n-tile = bid&1)
//               q = hid @ wk^T + bk -> q_hi fp16; qnorm atomics
//   bid >= 256: W2T tile (b = bid-256: n-tile = b>>2, m-tile = b&3)
//               w2t = wo @ mv^T -> fp16; early-exit n0 >= meta[1]
// ---------------------------------------------------------------------------
__global__ __launch_bounds__(256, 1)
void qw_kernel(const __half* __restrict__ hid, const __half* __restrict__ wk,
               const __half* __restrict__ wo, const __half* __restrict__ mvh,
               __half* __restrict__ qh, __half* __restrict__ w2t,
               const int* __restrict__ meta, const float* __restrict__ bk,
               float* __restrict__ qnorm)
{
    extern __shared__ char smem[];
    const uint32_t sb = su32(smem);
    const int t = threadIdx.x;
    const int wid = t >> 5, l = t & 31;
    const int wm = wid & 1, wn = wid >> 1;
    const int bid = blockIdx.x;
    const bool is_q = bid < 256;

    int m0, n0, Ntot;
    const __half *A, *B;
    if (is_q) {
        m0 = (bid >> 1) << 7; n0 = (bid & 1) << 8; Ntot = H_DIM;
        A = hid; B = wk;
    } else {
        const int b = bid - 256;
        n0 = (b >> 2) << 8;
        if (n0 >= __ldg(meta + 1)) return;
        m0 = (b & 3) << 7; Ntot = M_MEM;
        A = wo; B = mvh;
    }

    const uint32_t aoff = (uint32_t)(wm * 64 + (l & 7) + ((l >> 3) & 1) * 8) * TROW
                        + ((l >> 4) & 1) * 16;
    const uint32_t boff = (uint32_t)(wn * 64 + (l & 7) + ((l >> 4) & 1) * 8) * TROW
                        + ((l >> 3) & 1) * 16;

    float acc[4][8][4];
#pragma unroll
    for (int mf = 0; mf < 4; mf++)
#pragma unroll
        for (int nf = 0; nf < 8; nf++)
#pragma unroll
            for (int i = 0; i < 4; i++) acc[mf][nf][i] = 0.0f;

    gemm_mainloop(acc, sb, A, B, H_DIM, m0, n0, H_DIM, t, aoff, boff);

    __half* Ch = is_q ? qh : w2t;
#pragma unroll
    for (int mf = 0; mf < 4; mf++) {
        const int r0 = m0 + wm * 64 + mf * 16 + (l >> 2);
        float p0 = 0.f, p1 = 0.f;
#pragma unroll
        for (int nf = 0; nf < 8; nf++) {
            const int c0 = n0 + wn * 64 + nf * 8 + ((l & 3) << 1);
            float v0 = acc[mf][nf][0], v1 = acc[mf][nf][1];
            float v2 = acc[mf][nf][2], v3 = acc[mf][nf][3];
            if (is_q) {
                const float b0 = __ldg(bk + c0), b1 = __ldg(bk + c0 + 1);
                v0 += b0; v1 += b1; v2 += b0; v3 += b1;
                p0 += v0 * v0 + v1 * v1; p1 += v2 * v2 + v3 * v3;
            }
            *(__half2*)(Ch + (size_t)r0 * Ntot + c0) =
                __halves2half2(__float2half_rn(v0), __float2half_rn(v1));
            *(__half2*)(Ch + (size_t)(r0 + 8) * Ntot + c0) =
                __halves2half2(__float2half_rn(v2), __float2half_rn(v3));
        }
        if (is_q) {
            atomicAdd(qnorm + r0, p0);
            atomicAdd(qnorm + r0 + 8, p1);
        }
    }
}

// ---------------------------------------------------------------------------
// Scores kernel: e = col<mact ? exp(10*acc*rsqrt(qnorm)-10)*8192 : 0 -> fp16;
// rowsum atomics. Early-exit n0 >= meta[1].
// ---------------------------------------------------------------------------
__global__ __launch_bounds__(256, 1)
void scores_kernel(const __half* __restrict__ qh, const __half* __restrict__ mkh,
                   __half* __restrict__ expb,
                   const int* __restrict__ meta, const float* __restrict__ qnorm,
                   float* __restrict__ rowsum)
{
    extern __shared__ char smem[];
    const uint32_t sb = su32(smem);
    const int t = threadIdx.x;
    const int wid = t >> 5, l = t & 31;
    const int wm = wid & 1, wn = wid >> 1;
    const int m0 = blockIdx.y << 7, n0 = blockIdx.x << 8;
    if (n0 >= __ldg(meta + 1)) return;

    const uint32_t aoff = (uint32_t)(wm * 64 + (l & 7) + ((l >> 3) & 1) * 8) * TROW
                        + ((l >> 4) & 1) * 16;
    const uint32_t boff = (uint32_t)(wn * 64 + (l & 7) + ((l >> 4) & 1) * 8) * TROW
                        + ((l >> 3) & 1) * 16;

    float acc[4][8][4];
#pragma unroll
    for (int mf = 0; mf < 4; mf++)
#pragma unroll
        for (int nf = 0; nf < 8; nf++)
#pragma unroll
            for (int i = 0; i < 4; i++) acc[mf][nf][i] = 0.0f;

    gemm_mainloop(acc, sb, qh, mkh, H_DIM, m0, n0, H_DIM, t, aoff, boff);

    const int mact = __ldg(meta + 0);
#pragma unroll
    for (int mf = 0; mf < 4; mf++) {
        const int r0 = m0 + wm * 64 + mf * 16 + (l >> 2);
        const float rd0 = rsqrtf(__ldg(qnorm + r0) + 1e-6f);
        const float rd1 = rsqrtf(__ldg(qnorm + r0 + 8) + 1e-6f);
        float p0 = 0.f, p1 = 0.f;
#pragma unroll
        for (int nf = 0; nf < 8; nf++) {
            const int c0 = n0 + wn * 64 + nf * 8 + ((l & 3) << 1);
            const bool u0 = c0 < mact, u1 = (c0 + 1) < mact;
            const float e0 = u0 ? __expf(fmaf(acc[mf][nf][0] * rd0, 10.f, -10.f)) * EXP_SCALE : 0.f;
            const float e1 = u1 ? __expf(fmaf(acc[mf][nf][1] * rd0, 10.f, -10.f)) * EXP_SCALE : 0.f;
            const float e2 = u0 ? __expf(fmaf(acc[mf][nf][2] * rd1, 10.f, -10.f)) * EXP_SCALE : 0.f;
            const float e3 = u1 ? __expf(fmaf(acc[mf][nf][3] * rd1, 10.f, -10.f)) * EXP_SCALE : 0.f;
            *(__half2*)(expb + (size_t)r0 * M_MEM + c0) =
                __halves2half2(__float2half_rn(e0), __float2half_rn(e1));
            *(__half2*)(expb + (size_t)(r0 + 8) * M_MEM + c0) =
                __halves2half2(__float2half_rn(e2), __float2half_rn(e3));
            p0 += e0 + e1; p1 += e2 + e3;
        }
        atomicAdd(rowsum + r0, p0);
        atomicAdd(rowsum + r0 + 8, p1);
    }
}

// ---------------------------------------------------------------------------
// Retrieval kernel: out = (exp @ w2t^T) / rowsum + bo. Dynamic K = meta[1].
// ---------------------------------------------------------------------------
__global__ __launch_bounds__(256, 1)
void retr_kernel(const __half* __restrict__ expb, const __half* __restrict__ w2t,
                 float* __restrict__ out,
                 const int* __restrict__ meta, const float* __restrict__ bo,
                 const float* __restrict__ rowsum)
{
    extern __shared__ char smem[];
    const uint32_t sb = su32(smem);
    const int t = threadIdx.x;
    const int wid = t >> 5, l = t & 31;
    const int wm = wid & 1, wn = wid >> 1;
    const int m0 = blockIdx.y << 7, n0 = blockIdx.x << 8;
    const int K = __ldg(meta + 1);

    const uint32_t aoff = (uint32_t)(wm * 64 + (l & 7) + ((l >> 3) & 1) * 8) * TROW
                        + ((l >> 4) & 1) * 16;
    const uint32_t boff = (uint32_t)(wn * 64 + (l & 7) + ((l >> 4) & 1) * 8) * TROW
                        + ((l >> 3) & 1) * 16;

    float acc[4][8][4];
#pragma unroll
    for (int mf = 0; mf < 4; mf++)
#pragma unroll
        for (int nf = 0; nf < 8; nf++)
#pragma unroll
            for (int i = 0; i < 4; i++) acc[mf][nf][i] = 0.0f;

    gemm_mainloop(acc, sb, expb, w2t, M_MEM, m0, n0, K, t, aoff, boff);

#pragma unroll
    for (int mf = 0; mf < 4; mf++) {
        const int r0 = m0 + wm * 64 + mf * 16 + (l >> 2);
        const float rd0 = 1.0f / __ldg(rowsum + r0);
        const float rd1 = 1.0f / __ldg(rowsum + r0 + 8);
#pragma unroll
        for (int nf = 0; nf < 8; nf++) {
            const int c0 = n0 + wn * 64 + nf * 8 + ((l & 3) << 1);
            const float b0 = __ldg(bo + c0), b1 = __ldg(bo + c0 + 1);
            const float v0 = fmaf(acc[mf][nf][0], rd0, b0);
            const float v1 = fmaf(acc[mf][nf][1], rd0, b1);
            const float v2 = fmaf(acc[mf][nf][2], rd1, b0);
            const float v3 = fmaf(acc[mf][nf][3], rd1, b1);
            *(float2*)(out + (size_t)r0 * H_DIM + c0)       = make_float2(v0, v1);
            *(float2*)(out + (size_t)(r0 + 8) * H_DIM + c0) = make_float2(v2, v3);
        }
    }
}

// ---------------------------------------------------------------------------
// Launch pipeline
// ---------------------------------------------------------------------------
extern "C" void kernel_launch(void* const* d_in, const int* in_sizes, int n_in,
                              void* d_out, int out_size)
{
    const float* hidden = (const float*)d_in[0];
    const float* mk     = (const float*)d_in[1];
    const float* mv     = (const float*)d_in[2];
    const float* Wk     = (const float*)d_in[3];
    const float* bk     = (const float*)d_in[4];
    const float* Wo     = (const float*)d_in[5];
    const float* bo     = (const float*)d_in[6];
    const int*   usage  = (const int*)d_in[7];
    float* out = (float*)d_out;

    __half *hid_hi, *wk_hi, *wo_hi, *mv_hi, *mk_hi, *w2t_hi, *q_hi, *expp;
    float *qnormp, *rowsump;
    int *idxp, *metap;
    cudaGetSymbolAddress((void**)&hid_hi, g_hid_hi);
    cudaGetSymbolAddress((void**)&wk_hi, g_wk_hi);
    cudaGetSymbolAddress((void**)&wo_hi, g_wo_hi);
    cudaGetSymbolAddress((void**)&mv_hi, g_mv_hi);
    cudaGetSymbolAddress((void**)&mk_hi, g_mk_hi);
    cudaGetSymbolAddress((void**)&w2t_hi, g_w2t_hi);
    cudaGetSymbolAddress((void**)&q_hi, g_q_hi);
    cudaGetSymbolAddress((void**)&expp, g_exp);
    cudaGetSymbolAddress((void**)&qnormp, g_qnorm);
    cudaGetSymbolAddress((void**)&rowsump, g_rowsum);
    cudaGetSymbolAddress((void**)&idxp, g_idx);
    cudaGetSymbolAddress((void**)&metap, g_meta);

    cudaFuncSetAttribute(qw_kernel,     cudaFuncAttributeMaxDynamicSharedMemorySize, MM_SMEM1);
    cudaFuncSetAttribute(scores_kernel, cudaFuncAttributeMaxDynamicSharedMemorySize, MM_SMEM1);
    cudaFuncSetAttribute(retr_kernel,   cudaFuncAttributeMaxDynamicSharedMemorySize, MM_SMEM1);

    // 1: compaction (also zeros qnorm/rowsum)
    compact_kernel<<<1, 1024>>>(usage, idxp, metap, qnormp, rowsump);
    // 2: hidden -> fp16
    convert_hi_kernel<<<2048, 256>>>(hidden, hid_hi, T_TOK * H_DIM / 4);
    // 3: weights -> fp16
    prep_w_kernel<<<H_DIM * H_DIM / 4 / 256, 256>>>(Wk, Wo, wk_hi, wo_hi);
    // 4: bank gather/normalize -> fp16
    prep_bank_kernel<<<M_MEM, 128>>>(mv, mk, idxp, metap, mv_hi, mk_hi);
    // 5: combined qproj + W2T
    qw_kernel<<<256 + 64, 256, MM_SMEM1>>>(hid_hi, wk_hi, wo_hi, mv_hi,
                                           q_hi, w2t_hi, metap, bk, qnormp);
    // 6: exp scores (profiled slot)
    scores_kernel<<<dim3(M_MEM / 256, T_TOK / 128), 256, MM_SMEM1>>>(
        q_hi, mk_hi, expp, metap, qnormp, rowsump);
    // 7: retrieval
    retr_kernel<<<dim3(H_DIM / 256, T_TOK / 128), 256, MM_SMEM1>>>(
        expp, w2t_hi, out, metap, bo, rowsump);
}

// round 17
// speedup vs baseline: 1.0479x; 1.0479x over previous
#include <cuda_runtime.h>
#include <cuda_fp16.h>
#include <cstdint>

#define T_TOK 16384
#define H_DIM 512
#define M_MEM 4096
#define EXP_SCALE 8192.0f

// ---------------------------------------------------------------------------
// Scratch (static device globals; no allocations anywhere)
// ---------------------------------------------------------------------------
__device__ __half g_hid_hi[(size_t)T_TOK * H_DIM];
__device__ __half g_wk_hi[(size_t)H_DIM * H_DIM];
__device__ __half g_wo_hi[(size_t)H_DIM * H_DIM];
__device__ __half g_mv_hi[(size_t)M_MEM * H_DIM];   // compacted mv
__device__ __half g_mk_hi[(size_t)M_MEM * H_DIM];   // compacted, normalized mk (hi only)
__device__ __half g_w2t_hi[(size_t)H_DIM * M_MEM];  // W2T over compacted bank (hi only)
__device__ __half g_q_hi[(size_t)T_TOK * H_DIM];    // q (+bk), fp16, unnormalized
__device__ __half g_exp[(size_t)T_TOK * M_MEM];     // exp(logit-10)*8192, compacted cols
__device__ float  g_qnorm[T_TOK];                   // sum q^2 per row (atomic)
__device__ float  g_rowsum[T_TOK];                  // sum exp per row (atomic)
__device__ int    g_idx[M_MEM];                     // compacted slot -> original slot
__device__ int    g_meta[2];                        // [0]=M_active, [1]=pad256(M_active)

// ---------------------------------------------------------------------------
// Helpers (baseline PTX only: cp.async / ldmatrix / mma.sync)
// ---------------------------------------------------------------------------
__device__ __forceinline__ uint32_t su32(const void* p) {
    return (uint32_t)__cvta_generic_to_shared(p);
}
__device__ __forceinline__ void cp16(uint32_t dst, const void* src) {
    asm volatile("cp.async.cg.shared.global [%0], [%1], 16;\n" :: "r"(dst), "l"(src) : "memory");
}
__device__ __forceinline__ void cp_commit() { asm volatile("cp.async.commit_group;\n" ::: "memory"); }
__device__ __forceinline__ void cp_wait1()  { asm volatile("cp.async.wait_group 1;\n" ::: "memory"); }

__device__ __forceinline__ void ldsm_x4(uint32_t* r, uint32_t addr) {
    asm volatile("ldmatrix.sync.aligned.m8n8.x4.shared.b16 {%0,%1,%2,%3}, [%4];"
                 : "=r"(r[0]), "=r"(r[1]), "=r"(r[2]), "=r"(r[3]) : "r"(addr));
}
__device__ __forceinline__ void mma16816(float* c, const uint32_t* a, const uint32_t* b) {
    asm volatile(
        "mma.sync.aligned.m16n8k16.row.col.f32.f16.f16.f32 "
        "{%0,%1,%2,%3}, {%4,%5,%6,%7}, {%8,%9}, {%0,%1,%2,%3};"
        : "+f"(c[0]), "+f"(c[1]), "+f"(c[2]), "+f"(c[3])
        : "r"(a[0]), "r"(a[1]), "r"(a[2]), "r"(a[3]), "r"(b[0]), "r"(b[1]));
}

// ---------------------------------------------------------------------------
// Compaction + accumulator zeroing. 1024 threads, single CTA.
// ---------------------------------------------------------------------------
__global__ void compact_kernel(const int* __restrict__ usage, int* __restrict__ idx,
                               int* __restrict__ meta,
                               float* __restrict__ qnorm, float* __restrict__ rowsum)
{
    __shared__ int wsum[32];
    const int t = threadIdx.x, lane = t & 31, w = t >> 5;

#pragma unroll
    for (int i = 0; i < 16; i++) {
        qnorm[t + (i << 10)]  = 0.0f;
        rowsum[t + (i << 10)] = 0.0f;
    }

    const int base = t * 4;
    int f[4], cnt = 0;
#pragma unroll
    for (int i = 0; i < 4; i++) { f[i] = usage[base + i] > 0; cnt += f[i]; }
    int inc = cnt;
#pragma unroll
    for (int o = 1; o < 32; o <<= 1) {
        int v = __shfl_up_sync(0xffffffffu, inc, o);
        if (lane >= o) inc += v;
    }
    const int exc = inc - cnt;
    if (lane == 31) wsum[w] = inc;
    __syncthreads();
    if (w == 0) {
        int v = wsum[lane];
        __syncwarp();
#pragma unroll
        for (int o = 1; o < 32; o <<= 1) {
            int u = __shfl_up_sync(0xffffffffu, v, o);
            if (lane >= o) v += u;
        }
        wsum[lane] = v;
    }
    __syncthreads();
    int pos = (w > 0 ? wsum[w - 1] : 0) + exc;
#pragma unroll
    for (int i = 0; i < 4; i++)
        if (f[i]) idx[pos++] = base + i;
    if (t == 1023) {
        const int tot = wsum[31];
        meta[0] = tot;
        int pad = ((tot + 255) >> 8) << 8;
        meta[1] = pad < 256 ? 256 : pad;
    }
}

// ---------------------------------------------------------------------------
// Bank prep: block j -> compacted row j: mv fp16 hi, mk normalized fp16 hi.
// ---------------------------------------------------------------------------
__global__ void prep_bank_kernel(const float* __restrict__ mv, const float* __restrict__ mk,
                                 const int* __restrict__ idx, const int* __restrict__ meta,
                                 __half* __restrict__ mvh, __half* __restrict__ mkh)
{
    __shared__ float sh[4];
    const int j = blockIdx.x, tid = threadIdx.x;
    const size_t off = (size_t)j * H_DIM + tid * 4;
    if (j >= meta[0]) {
        const __half2 z = __halves2half2(__float2half_rn(0.f), __float2half_rn(0.f));
        *(__half2*)(mvh + off + 0) = z; *(__half2*)(mvh + off + 2) = z;
        *(__half2*)(mkh + off + 0) = z; *(__half2*)(mkh + off + 2) = z;
        return;
    }
    const int row = idx[j];
    {
        float4 v = ((const float4*)(mv + (size_t)row * H_DIM))[tid];
        *(__half2*)(mvh + off + 0) = __halves2half2(__float2half_rn(v.x), __float2half_rn(v.y));
        *(__half2*)(mvh + off + 2) = __halves2half2(__float2half_rn(v.z), __float2half_rn(v.w));
    }
    {
        float4 v = ((const float4*)(mk + (size_t)row * H_DIM))[tid];
        float s = v.x * v.x + v.y * v.y + v.z * v.z + v.w * v.w;
#pragma unroll
        for (int o = 16; o; o >>= 1) s += __shfl_xor_sync(0xffffffffu, s, o);
        if ((tid & 31) == 0) sh[tid >> 5] = s;
        __syncthreads();
        const float r = rsqrtf(sh[0] + sh[1] + sh[2] + sh[3] + 1e-6f);
        *(__half2*)(mkh + off + 0) = __halves2half2(__float2half_rn(v.x * r), __float2half_rn(v.y * r));
        *(__half2*)(mkh + off + 2) = __halves2half2(__float2half_rn(v.z * r), __float2half_rn(v.w * r));
    }
}

// ---------------------------------------------------------------------------
// Weights prep: Wk -> hi, Wo -> hi. One thread per float4 of each.
// ---------------------------------------------------------------------------
__global__ void prep_w_kernel(const float* __restrict__ Wk, const float* __restrict__ Wo,
                              __half* __restrict__ wkh, __half* __restrict__ woh)
{
    const int idx = blockIdx.x * blockDim.x + threadIdx.x;
    {
        float4 v = ((const float4*)Wk)[idx];
        ((__half2*)wkh)[idx * 2 + 0] = __halves2half2(__float2half_rn(v.x), __float2half_rn(v.y));
        ((__half2*)wkh)[idx * 2 + 1] = __halves2half2(__float2half_rn(v.z), __float2half_rn(v.w));
    }
    {
        float4 v = ((const float4*)Wo)[idx];
        ((__half2*)woh)[idx * 2 + 0] = __halves2half2(__float2half_rn(v.x), __float2half_rn(v.y));
        ((__half2*)woh)[idx * 2 + 1] = __halves2half2(__float2half_rn(v.z), __float2half_rn(v.w));
    }
}

// ---------------------------------------------------------------------------
// Elementwise fp32 -> fp16 (hidden)
// ---------------------------------------------------------------------------
__global__ void convert_hi_kernel(const float* __restrict__ in, __half* __restrict__ oh, int n4)
{
    int idx = blockIdx.x * blockDim.x + threadIdx.x;
    const int stride = gridDim.x * blockDim.x;
    for (; idx < n4; idx += stride) {
        float4 v = ((const float4*)in)[idx];
        ((__half2*)oh)[idx * 2 + 0] = __halves2half2(__float2half_rn(v.x), __float2half_rn(v.y));
        ((__half2*)oh)[idx * 2 + 1] = __halves2half2(__float2half_rn(v.z), __float2half_rn(v.w));
    }
}

// ---------------------------------------------------------------------------
// Shared GEMM machinery: CTA tile 128x128, 4 warps (2x2) of 64x64, BK=64,
// 128 threads, 2 CTAs/SM, 3-stage single-sync cp.async pipeline, fp32 accum.
// ---------------------------------------------------------------------------
#define BK       64
#define TROW     144
#define A_TSZ    (128 * TROW)              // 18432 B
#define B_TSZ    (128 * TROW)              // 18432 B
#define STG1     (A_TSZ + B_TSZ)           // 36864 B
#define MM_SMEM1 (3 * STG1)                // 110592 B -> 2 CTAs/SM

__device__ __forceinline__ void load_chunk(uint32_t st,
    const __half* __restrict__ A, const __half* __restrict__ B,
    int LD, int m0, int n0, int k0, int t)
{
#pragma unroll
    for (int i = 0; i < 8; i++) {
        const int idx = (i << 7) + t;
        const int row = idx >> 3, j = idx & 7;
        cp16(st + (uint32_t)(row * TROW + j * 16),
             A + (size_t)(m0 + row) * LD + k0 + (j << 3));
    }
#pragma unroll
    for (int i = 0; i < 8; i++) {
        const int idx = (i << 7) + t;
        const int row = idx >> 3, j = idx & 7;
        cp16(st + A_TSZ + (uint32_t)(row * TROW + j * 16),
             B + (size_t)(n0 + row) * LD + k0 + (j << 3));
    }
}

__device__ __forceinline__ void gemm_mainloop(
    float acc[4][8][4], uint32_t sb,
    const __half* __restrict__ A, const __half* __restrict__ B,
    int LD, int m0, int n0, int K, int t,
    uint32_t aoff, uint32_t boff)
{
    const int nch = K / BK;
    load_chunk(sb, A, B, LD, m0, n0, 0, t);         cp_commit();
    load_chunk(sb + STG1, A, B, LD, m0, n0, BK, t); cp_commit();
    for (int c = 0; c < nch; c++) {
        cp_wait1();
        __syncthreads();
        if (c + 2 < nch)
            load_chunk(sb + (uint32_t)((c + 2) % 3) * STG1, A, B,
                       LD, m0, n0, (c + 2) * BK, t);
        cp_commit();
        const uint32_t st = sb + (uint32_t)(c % 3) * STG1;
#pragma unroll
        for (int ks = 0; ks < 4; ks++) {
            uint32_t ah[4][4], bh[4][4];
#pragma unroll
            for (int mf = 0; mf < 4; mf++)
                ldsm_x4(ah[mf], st + aoff + mf * (16 * TROW) + ks * 32);
#pragma unroll
            for (int nf2 = 0; nf2 < 4; nf2++)
                ldsm_x4(bh[nf2], st + A_TSZ + boff + nf2 * (16 * TROW) + ks * 32);
#pragma unroll
            for (int mf = 0; mf < 4; mf++)
#pragma unroll
                for (int nf = 0; nf < 8; nf++)
                    mma16816(acc[mf][nf], ah[mf], &bh[nf >> 1][(nf & 1) * 2]);
        }
    }
}

// ---------------------------------------------------------------------------
// Combined qproj + W2T kernel. 1D grid of 512+128 blocks.
//   bid < 512 : qproj tile  (m-tile = bid>>2, n-tile = bid&3)
//   bid >= 512: W2T tile (b: n-tile = b>>2, m-tile = b&3); early-exit vs meta[1]
// ---------------------------------------------------------------------------
__global__ __launch_bounds__(128, 2)
void qw_kernel(const __half* __restrict__ hid, const __half* __restrict__ wk,
               const __half* __restrict__ wo, const __half* __restrict__ mvh,
               __half* __restrict__ qh, __half* __restrict__ w2t,
               const int* __restrict__ meta, const float* __restrict__ bk,
               float* __restrict__ qnorm)
{
    extern __shared__ char smem[];
    const uint32_t sb = su32(smem);
    const int t = threadIdx.x;
    const int wid = t >> 5, l = t & 31;
    const int wm = wid & 1, wn = wid >> 1;
    const int bid = blockIdx.x;
    const bool is_q = bid < 512;

    int m0, n0, Ntot;
    const __half *A, *B;
    if (is_q) {
        m0 = (bid >> 2) << 7; n0 = (bid & 3) << 7; Ntot = H_DIM;
        A = hid; B = wk;
    } else {
        const int b = bid - 512;
        n0 = (b >> 2) << 7;
        if (n0 >= __ldg(meta + 1)) return;
        m0 = (b & 3) << 7; Ntot = M_MEM;
        A = wo; B = mvh;
    }

    const uint32_t aoff = (uint32_t)(wm * 64 + (l & 7) + ((l >> 3) & 1) * 8) * TROW
                        + ((l >> 4) & 1) * 16;
    const uint32_t boff = (uint32_t)(wn * 64 + (l & 7) + ((l >> 4) & 1) * 8) * TROW
                        + ((l >> 3) & 1) * 16;

    float acc[4][8][4];
#pragma unroll
    for (int mf = 0; mf < 4; mf++)
#pragma unroll
        for (int nf = 0; nf < 8; nf++)
#pragma unroll
            for (int i = 0; i < 4; i++) acc[mf][nf][i] = 0.0f;

    gemm_mainloop(acc, sb, A, B, H_DIM, m0, n0, H_DIM, t, aoff, boff);

    __half* Ch = is_q ? qh : w2t;
#pragma unroll
    for (int mf = 0; mf < 4; mf++) {
        const int r0 = m0 + wm * 64 + mf * 16 + (l >> 2);
        float p0 = 0.f, p1 = 0.f;
#pragma unroll
        for (int nf = 0; nf < 8; nf++) {
            const int c0 = n0 + wn * 64 + nf * 8 + ((l & 3) << 1);
            float v0 = acc[mf][nf][0], v1 = acc[mf][nf][1];
            float v2 = acc[mf][nf][2], v3 = acc[mf][nf][3];
            if (is_q) {
                const float b0 = __ldg(bk + c0), b1 = __ldg(bk + c0 + 1);
                v0 += b0; v1 += b1; v2 += b0; v3 += b1;
                p0 += v0 * v0 + v1 * v1; p1 += v2 * v2 + v3 * v3;
            }
            *(__half2*)(Ch + (size_t)r0 * Ntot + c0) =
                __halves2half2(__float2half_rn(v0), __float2half_rn(v1));
            *(__half2*)(Ch + (size_t)(r0 + 8) * Ntot + c0) =
                __halves2half2(__float2half_rn(v2), __float2half_rn(v3));
        }
        if (is_q) {
            atomicAdd(qnorm + r0, p0);
            atomicAdd(qnorm + r0 + 8, p1);
        }
    }
}

// ---------------------------------------------------------------------------
// Scores kernel: e = col<mact ? exp(10*acc*rsqrt(qnorm)-10)*8192 : 0 -> fp16;
// rowsum atomics. Early-exit n0 >= meta[1].
// ---------------------------------------------------------------------------
__global__ __launch_bounds__(128, 2)
void scores_kernel(const __half* __restrict__ qh, const __half* __restrict__ mkh,
                   __half* __restrict__ expb,
                   const int* __restrict__ meta, const float* __restrict__ qnorm,
                   float* __restrict__ rowsum)
{
    extern __shared__ char smem[];
    const uint32_t sb = su32(smem);
    const int t = threadIdx.x;
    const int wid = t >> 5, l = t & 31;
    const int wm = wid & 1, wn = wid >> 1;
    const int m0 = blockIdx.y << 7, n0 = blockIdx.x << 7;
    if (n0 >= __ldg(meta + 1)) return;

    const uint32_t aoff = (uint32_t)(wm * 64 + (l & 7) + ((l >> 3) & 1) * 8) * TROW
                        + ((l >> 4) & 1) * 16;
    const uint32_t boff = (uint32_t)(wn * 64 + (l & 7) + ((l >> 4) & 1) * 8) * TROW
                        + ((l >> 3) & 1) * 16;

    float acc[4][8][4];
#pragma unroll
    for (int mf = 0; mf < 4; mf++)
#pragma unroll
        for (int nf = 0; nf < 8; nf++)
#pragma unroll
            for (int i = 0; i < 4; i++) acc[mf][nf][i] = 0.0f;

    gemm_mainloop(acc, sb, qh, mkh, H_DIM, m0, n0, H_DIM, t, aoff, boff);

    const int mact = __ldg(meta + 0);
#pragma unroll
    for (int mf = 0; mf < 4; mf++) {
        const int r0 = m0 + wm * 64 + mf * 16 + (l >> 2);
        const float rd0 = rsqrtf(__ldg(qnorm + r0) + 1e-6f);
        const float rd1 = rsqrtf(__ldg(qnorm + r0 + 8) + 1e-6f);
        float p0 = 0.f, p1 = 0.f;
#pragma unroll
        for (int nf = 0; nf < 8; nf++) {
            const int c0 = n0 + wn * 64 + nf * 8 + ((l & 3) << 1);
            const bool u0 = c0 < mact, u1 = (c0 + 1) < mact;
            const float e0 = u0 ? __expf(fmaf(acc[mf][nf][0] * rd0, 10.f, -10.f)) * EXP_SCALE : 0.f;
            const float e1 = u1 ? __expf(fmaf(acc[mf][nf][1] * rd0, 10.f, -10.f)) * EXP_SCALE : 0.f;
            const float e2 = u0 ? __expf(fmaf(acc[mf][nf][2] * rd1, 10.f, -10.f)) * EXP_SCALE : 0.f;
            const float e3 = u1 ? __expf(fmaf(acc[mf][nf][3] * rd1, 10.f, -10.f)) * EXP_SCALE : 0.f;
            *(__half2*)(expb + (size_t)r0 * M_MEM + c0) =
                __halves2half2(__float2half_rn(e0), __float2half_rn(e1));
            *(__half2*)(expb + (size_t)(r0 + 8) * M_MEM + c0) =
                __halves2half2(__float2half_rn(e2), __float2half_rn(e3));
            p0 += e0 + e1; p1 += e2 + e3;
        }
        atomicAdd(rowsum + r0, p0);
        atomicAdd(rowsum + r0 + 8, p1);
    }
}

// ---------------------------------------------------------------------------
// Retrieval kernel: out = (exp @ w2t^T) / rowsum + bo. Dynamic K = meta[1].
// ---------------------------------------------------------------------------
__global__ __launch_bounds__(128, 2)
void retr_kernel(const __half* __restrict__ expb, const __half* __restrict__ w2t,
                 float* __restrict__ out,
                 const int* __restrict__ meta, const float* __restrict__ bo,
                 const float* __restrict__ rowsum)
{
    extern __shared__ char smem[];
    const uint32_t sb = su32(smem);
    const int t = threadIdx.x;
    const int wid = t >> 5, l = t & 31;
    const int wm = wid & 1, wn = wid >> 1;
    const int m0 = blockIdx.y << 7, n0 = blockIdx.x << 7;
    const int K = __ldg(meta + 1);

    const uint32_t aoff = (uint32_t)(wm * 64 + (l & 7) + ((l >> 3) & 1) * 8) * TROW
                        + ((l >> 4) & 1) * 16;
    const uint32_t boff = (uint32_t)(wn * 64 + (l & 7) + ((l >> 4) & 1) * 8) * TROW
                        + ((l >> 3) & 1) * 16;

    float acc[4][8][4];
#pragma unroll
    for (int mf = 0; mf < 4; mf++)
#pragma unroll
        for (int nf = 0; nf < 8; nf++)
#pragma unroll
            for (int i = 0; i < 4; i++) acc[mf][nf][i] = 0.0f;

    gemm_mainloop(acc, sb, expb, w2t, M_MEM, m0, n0, K, t, aoff, boff);

#pragma unroll
    for (int mf = 0; mf < 4; mf++) {
        const int r0 = m0 + wm * 64 + mf * 16 + (l >> 2);
        const float rd0 = 1.0f / __ldg(rowsum + r0);
        const float rd1 = 1.0f / __ldg(rowsum + r0 + 8);
#pragma unroll
        for (int nf = 0; nf < 8; nf++) {
            const int c0 = n0 + wn * 64 + nf * 8 + ((l & 3) << 1);
            const float b0 = __ldg(bo + c0), b1 = __ldg(bo + c0 + 1);
            const float v0 = fmaf(acc[mf][nf][0], rd0, b0);
            const float v1 = fmaf(acc[mf][nf][1], rd0, b1);
            const float v2 = fmaf(acc[mf][nf][2], rd1, b0);
            const float v3 = fmaf(acc[mf][nf][3], rd1, b1);
            *(float2*)(out + (size_t)r0 * H_DIM + c0)       = make_float2(v0, v1);
            *(float2*)(out + (size_t)(r0 + 8) * H_DIM + c0) = make_float2(v2, v3);
        }
    }
}

// ---------------------------------------------------------------------------
// Launch pipeline
// ---------------------------------------------------------------------------
extern "C" void kernel_launch(void* const* d_in, const int* in_sizes, int n_in,
                              void* d_out, int out_size)
{
    const float* hidden = (const float*)d_in[0];
    const float* mk     = (const float*)d_in[1];
    const float* mv     = (const float*)d_in[2];
    const float* Wk     = (const float*)d_in[3];
    const float* bk     = (const float*)d_in[4];
    const float* Wo     = (const float*)d_in[5];
    const float* bo     = (const float*)d_in[6];
    const int*   usage  = (const int*)d_in[7];
    float* out = (float*)d_out;

    __half *hid_hi, *wk_hi, *wo_hi, *mv_hi, *mk_hi, *w2t_hi, *q_hi, *expp;
    float *qnormp, *rowsump;
    int *idxp, *metap;
    cudaGetSymbolAddress((void**)&hid_hi, g_hid_hi);
    cudaGetSymbolAddress((void**)&wk_hi, g_wk_hi);
    cudaGetSymbolAddress((void**)&wo_hi, g_wo_hi);
    cudaGetSymbolAddress((void**)&mv_hi, g_mv_hi);
    cudaGetSymbolAddress((void**)&mk_hi, g_mk_hi);
    cudaGetSymbolAddress((void**)&w2t_hi, g_w2t_hi);
    cudaGetSymbolAddress((void**)&q_hi, g_q_hi);
    cudaGetSymbolAddress((void**)&expp, g_exp);
    cudaGetSymbolAddress((void**)&qnormp, g_qnorm);
    cudaGetSymbolAddress((void**)&rowsump, g_rowsum);
    cudaGetSymbolAddress((void**)&idxp, g_idx);
    cudaGetSymbolAddress((void**)&metap, g_meta);

    cudaFuncSetAttribute(qw_kernel,     cudaFuncAttributeMaxDynamicSharedMemorySize, MM_SMEM1);
    cudaFuncSetAttribute(scores_kernel, cudaFuncAttributeMaxDynamicSharedMemorySize, MM_SMEM1);
    cudaFuncSetAttribute(retr_kernel,   cudaFuncAttributeMaxDynamicSharedMemorySize, MM_SMEM1);

    // 1: compaction (also zeros qnorm/rowsum)
    compact_kernel<<<1, 1024>>>(usage, idxp, metap, qnormp, rowsump);
    // 2: hidden -> fp16
    convert_hi_kernel<<<2048, 256>>>(hidden, hid_hi, T_TOK * H_DIM / 4);
    // 3: weights -> fp16
    prep_w_kernel<<<H_DIM * H_DIM / 4 / 256, 256>>>(Wk, Wo, wk_hi, wo_hi);
    // 4: bank gather/normalize -> fp16
    prep_bank_kernel<<<M_MEM, 128>>>(mv, mk, idxp, metap, mv_hi, mk_hi);
    // 5: combined qproj + W2T
    qw_kernel<<<512 + 128, 128, MM_SMEM1>>>(hid_hi, wk_hi, wo_hi, mv_hi,
                                            q_hi, w2t_hi, metap, bk, qnormp);
    // 6: exp scores
    scores_kernel<<<dim3(M_MEM / 128, T_TOK / 128), 128, MM_SMEM1>>>(
        q_hi, mk_hi, expp, metap, qnormp, rowsump);
    // 7: retrieval
    retr_kernel<<<dim3(H_DIM / 128, T_TOK / 128), 128, MM_SMEM1>>>(
        expp, w2t_hi, out, metap, bo, rowsump);
}